// round 1
// baseline (speedup 1.0000x reference)
#include <cuda_runtime.h>
#include <cstdint>

#define BB 16
#define CC 80
#define TX 512
#define TY 2048
#define NEGF (-1000000000.0f)

// Output layout (flat concat, fp32):
// z_T [B,TY,C], y_mean_T [B,TY,C], y_ls_T [B,TY,C], attn_T [B,TY,TX], dur [B,TX,1]
#define N_ZT   ((size_t)BB * TY * CC)          // 2,621,440
#define OFF_Z   ((size_t)0)
#define OFF_M   (N_ZT)
#define OFF_L   (2 * N_ZT)
#define OFF_AT  (3 * N_ZT)                      // 7,864,320
#define OFF_DUR (3 * N_ZT + (size_t)BB * TY * TX)  // 24,641,536

// ---------------- scratch (device globals, no allocation) ----------------
__device__ float g_a   [BB * CC * TX];   // exp(-2*log_scale)
__device__ float g_ms  [BB * CC * TX];   // mean * scale
__device__ float g_bias[BB * TX];        // logp1 + logp4 per (b,x)
__device__ float g_logp[(size_t)BB * TY * TX]; // masked logp, layout [b][y][x]
__device__ int   g_xs  [BB * TY];        // backtrack: x index per (b,s), -1 inactive

// ---------------- f32x2 helpers ----------------
__device__ __forceinline__ unsigned long long pack2(float lo, float hi) {
    unsigned long long r;
    asm("mov.b64 %0, {%1, %2};" : "=l"(r) : "f"(lo), "f"(hi));
    return r;
}
__device__ __forceinline__ float2 unpack2(unsigned long long v) {
    float lo, hi;
    asm("mov.b64 {%0, %1}, %2;" : "=f"(lo), "=f"(hi) : "l"(v));
    return make_float2(lo, hi);
}
__device__ __forceinline__ unsigned long long fma2(unsigned long long a,
                                                   unsigned long long b,
                                                   unsigned long long c) {
    unsigned long long d;
    asm("fma.rn.f32x2 %0, %1, %2, %3;" : "=l"(d) : "l"(a), "l"(b), "l"(c));
    return d;
}

// ---------------- kernel 1: prep (scale arrays + bias) ----------------
__global__ void __launch_bounds__(128) prep_kernel(const float* __restrict__ om,
                                                   const float* __restrict__ ols) {
    int b = blockIdx.y;
    int x = blockIdx.x * 128 + threadIdx.x;
    float acc = 0.0f;
    for (int c = 0; c < CC; ++c) {
        size_t i = ((size_t)b * CC + c) * TX + x;
        float ls = ols[i];
        float m  = om[i];
        float a  = expf(-2.0f * ls);
        g_a[i]  = a;
        g_ms[i] = m * a;
        acc += -0.9189385332046727f - ls - 0.5f * m * m * a;
    }
    g_bias[b * TX + x] = acc;
}

// ---------------- kernel 2: logp GEMM (f32x2) ----------------
// logp[b][y][x] = mask * (bias[b][x] + sum_c a[c][x]*(-0.5 z^2[c][y]) + ms[c][x]*z[c][y])
#define GBX 128
#define GBY 64
#define GKC 16
__global__ void __launch_bounds__(256, 2) gemm_logp(const float* __restrict__ z,
                                                    const int* __restrict__ xlen,
                                                    const int* __restrict__ ylen) {
    __shared__ __align__(16) float As[GKC][GBX];
    __shared__ __align__(16) float Ms[GKC][GBX];
    __shared__ __align__(16) unsigned long long Z2[GKC][GBY]; // -0.5 z^2, dup in both halves
    __shared__ __align__(16) unsigned long long Z1[GKC][GBY]; // z, dup

    int b  = blockIdx.z;
    int x0 = blockIdx.x * GBX;
    int y0 = blockIdx.y * GBY;
    int tid = threadIdx.x;
    int txi = tid & 15;        // 16 x-groups
    int tyi = tid >> 4;        // 16 y-groups
    int xl = txi * 8;          // 8 consecutive x per thread
    int yl = tyi * 4;          // 4 consecutive y per thread

    unsigned long long acc[4][4];
#pragma unroll
    for (int i = 0; i < 4; ++i)
#pragma unroll
        for (int j = 0; j < 4; ++j) acc[i][j] = 0ULL;

    for (int kc = 0; kc < CC; kc += GKC) {
        __syncthreads();
        // load A/M tiles: 16 rows x 128 cols = 512 float4s; 2 per thread
#pragma unroll
        for (int i = 0; i < 2; ++i) {
            int f  = tid + i * 256;
            int r  = f >> 5;
            int c4 = (f & 31) << 2;
            size_t gi = ((size_t)b * CC + kc + r) * TX + x0 + c4;
            float4 av = *(const float4*)&g_a[gi];
            float4 mv = *(const float4*)&g_ms[gi];
            *(float4*)&As[r][c4] = av;
            *(float4*)&Ms[r][c4] = mv;
        }
        // load Z tiles: 16 rows x 64 cols = 256 float4s; 1 per thread (duplicated pack)
        {
            int r  = tid >> 4;
            int c4 = (tid & 15) << 2;
            size_t gi = ((size_t)b * CC + kc + r) * TY + y0 + c4;
            float4 zv = *(const float4*)&z[gi];
            Z1[r][c4 + 0] = pack2(zv.x, zv.x);
            Z1[r][c4 + 1] = pack2(zv.y, zv.y);
            Z1[r][c4 + 2] = pack2(zv.z, zv.z);
            Z1[r][c4 + 3] = pack2(zv.w, zv.w);
            Z2[r][c4 + 0] = pack2(-0.5f * zv.x * zv.x, -0.5f * zv.x * zv.x);
            Z2[r][c4 + 1] = pack2(-0.5f * zv.y * zv.y, -0.5f * zv.y * zv.y);
            Z2[r][c4 + 2] = pack2(-0.5f * zv.z * zv.z, -0.5f * zv.z * zv.z);
            Z2[r][c4 + 3] = pack2(-0.5f * zv.w * zv.w, -0.5f * zv.w * zv.w);
        }
        __syncthreads();
#pragma unroll
        for (int k = 0; k < GKC; ++k) {
            ulonglong2 a0 = *(const ulonglong2*)&As[k][xl];
            ulonglong2 a1 = *(const ulonglong2*)&As[k][xl + 4];
            ulonglong2 m0 = *(const ulonglong2*)&Ms[k][xl];
            ulonglong2 m1 = *(const ulonglong2*)&Ms[k][xl + 4];
            ulonglong2 q0 = *(const ulonglong2*)&Z2[k][yl];
            ulonglong2 q1 = *(const ulonglong2*)&Z2[k][yl + 2];
            ulonglong2 p0 = *(const ulonglong2*)&Z1[k][yl];
            ulonglong2 p1 = *(const ulonglong2*)&Z1[k][yl + 2];
            unsigned long long aa[4] = {a0.x, a0.y, a1.x, a1.y};
            unsigned long long mm[4] = {m0.x, m0.y, m1.x, m1.y};
            unsigned long long zz[4] = {q0.x, q0.y, q1.x, q1.y};
            unsigned long long z1v[4] = {p0.x, p0.y, p1.x, p1.y};
#pragma unroll
            for (int xp = 0; xp < 4; ++xp)
#pragma unroll
                for (int yy = 0; yy < 4; ++yy) {
                    acc[xp][yy] = fma2(aa[xp], zz[yy], acc[xp][yy]);
                    acc[xp][yy] = fma2(mm[xp], z1v[yy], acc[xp][yy]);
                }
        }
    }

    // epilogue: add bias, mask, store
    int txL = xlen[b], tyL = ylen[b];
    float bv[8];
    *(float4*)&bv[0] = *(const float4*)&g_bias[b * TX + x0 + xl];
    *(float4*)&bv[4] = *(const float4*)&g_bias[b * TX + x0 + xl + 4];
#pragma unroll
    for (int yy = 0; yy < 4; ++yy) {
        int y = y0 + yl + yy;
        bool yok = (y < tyL);
        float row[8];
#pragma unroll
        for (int xp = 0; xp < 4; ++xp) {
            float2 u = unpack2(acc[xp][yy]);
            row[2 * xp]     = u.x;
            row[2 * xp + 1] = u.y;
        }
        float o[8];
#pragma unroll
        for (int j = 0; j < 8; ++j) {
            int x = x0 + xl + j;
            o[j] = (yok && x < txL) ? (bv[j] + row[j]) : 0.0f;
        }
        size_t base = ((size_t)b * TY + y) * TX + x0 + xl;
        *(float4*)&g_logp[base]     = make_float4(o[0], o[1], o[2], o[3]);
        *(float4*)&g_logp[base + 4] = make_float4(o[4], o[5], o[6], o[7]);
    }
}

// ---------------- kernel 3: forward DP + backtrack (fused, per-batch) ----------------
// dyn smem: sd[TY*16] uint (decision bits) | v[2*512] float | dur[512] int
#define FWD_SMEM (TY * 16 * 4 + 2 * TX * 4 + TX * 4)
__global__ void __launch_bounds__(512) fwd_kernel(const int* __restrict__ xlen,
                                                  const int* __restrict__ ylen,
                                                  float* __restrict__ out_dur) {
    extern __shared__ unsigned char smem_raw[];
    unsigned* sd = (unsigned*)smem_raw;                       // TY*16 words
    float* v = (float*)(smem_raw + (size_t)TY * 16 * 4);      // 2*512
    int* dur = (int*)(smem_raw + (size_t)TY * 16 * 4 + 2 * TX * 4);

    int b = blockIdx.x;
    int tid = threadIdx.x;
    int warp = tid >> 5, lane = tid & 31;
    dur[tid] = 0;

    const float* lp = &g_logp[(size_t)b * TY * TX];

    float nxt[8];
#pragma unroll
    for (int j = 0; j < 8; ++j) nxt[j] = lp[(size_t)j * TX + tid];

    int cur = 0;
    for (int g = 0; g < TY; g += 8) {
        float cv[8];
#pragma unroll
        for (int j = 0; j < 8; ++j) cv[j] = nxt[j];
        if (g + 8 < TY) {
#pragma unroll
            for (int j = 0; j < 8; ++j) nxt[j] = lp[(size_t)(g + 8 + j) * TX + tid];
        }
#pragma unroll
        for (int j = 0; j < 8; ++j) {
            int y = g + j;
            if (y == 0) {
                v[tid] = (tid == 0) ? cv[0] : NEGF;
                __syncthreads();
            } else {
                float vs = v[cur * TX + tid];
                float vd = (tid > 0) ? v[cur * TX + tid - 1] : NEGF;
                unsigned bal = __ballot_sync(0xffffffffu, vd > vs);
                if (lane == 0) sd[(y - 1) * 16 + warp] = bal;
                float vn = cv[j] + fmaxf(vs, vd);
                v[(cur ^ 1) * TX + tid] = vn;
                __syncthreads();
                cur ^= 1;
            }
        }
    }

    int txL = xlen[b], tyL = ylen[b];
    if (tid == 0) {
        int idx = txL - 1;
        for (int y = TY - 1; y >= 0; --y) {
            if (y >= tyL) { g_xs[b * TY + y] = -1; continue; }
            g_xs[b * TY + y] = idx;
            dur[idx]++;
            int mv = 0;
            if (idx > 0) {
                if (idx == y) {
                    mv = 1;
                } else {
                    unsigned w = sd[(y - 1) * 16 + (idx >> 5)];
                    mv = (w >> (idx & 31)) & 1;
                }
            }
            idx -= mv;
        }
    }
    __syncthreads();
    float dv = log1pf((float)dur[tid]);
    out_dur[b * TX + tid] = (tid < txL) ? dv : 0.0f;
}

// ---------------- kernel 4: outputs (attn rows, z transpose, gathers) ----------------
__global__ void __launch_bounds__(512) out_kernel(const float* __restrict__ z,
                                                  const float* __restrict__ om,
                                                  const float* __restrict__ ols,
                                                  const int* __restrict__ ylen,
                                                  float* __restrict__ out) {
    int bs = blockIdx.x;
    int b = bs >> 11;          // / TY
    int s = bs & (TY - 1);
    int tid = threadIdx.x;
    int xsv = g_xs[bs];

    // attn_T [B,TY,TX]
    out[OFF_AT + (size_t)bs * TX + tid] = (tid == xsv) ? 1.0f : 0.0f;

    if (tid < CC) {
        int tyL = ylen[b];
        float zv = (s < tyL) ? z[((size_t)b * CC + tid) * TY + s] : 0.0f;
        out[OFF_Z + (size_t)bs * CC + tid] = zv;
        float mv = 0.0f, lv = 0.0f;
        if (xsv >= 0) {
            size_t gi = ((size_t)b * CC + tid) * TX + xsv;
            mv = om[gi];
            lv = ols[gi];
        }
        out[OFF_M + (size_t)bs * CC + tid] = mv;
        out[OFF_L + (size_t)bs * CC + tid] = lv;
    }
}

// ---------------- launch ----------------
extern "C" void kernel_launch(void* const* d_in, const int* in_sizes, int n_in,
                              void* d_out, int out_size) {
    const float* om   = (const float*)d_in[0];
    const float* ols  = (const float*)d_in[1];
    const float* z    = (const float*)d_in[2];
    const int*   xlen = (const int*)d_in[3];
    const int*   ylen = (const int*)d_in[4];
    float* out = (float*)d_out;

    prep_kernel<<<dim3(TX / 128, BB), 128>>>(om, ols);
    gemm_logp<<<dim3(TX / GBX, TY / GBY, BB), 256>>>(z, xlen, ylen);

    static bool attr_set = false;
    if (!attr_set) {
        cudaFuncSetAttribute(fwd_kernel, cudaFuncAttributeMaxDynamicSharedMemorySize, FWD_SMEM);
        attr_set = true;
    }
    fwd_kernel<<<BB, TX, FWD_SMEM>>>(xlen, ylen, out + OFF_DUR);
    out_kernel<<<BB * TY, TX>>>(z, om, ols, ylen, out);
}